// round 7
// baseline (speedup 1.0000x reference)
#include <cuda_runtime.h>

// Scratch for the extracted diagonal (allocation-free: __device__ global).
__device__ float g_diag[4096];

// Kernel A: pull diag(W) out of the dense [4096,4096] matrix.
__global__ void extract_diag_kernel(const float* __restrict__ W) {
    int j = blockIdx.x * blockDim.x + threadIdx.x;
    if (j < 4096) {
        g_diag[j] = __ldg(&W[(size_t)j * 4097u]);
    }
}

// Kernel B: y = x * diag (columnwise), persistent grid-stride stream.
// Total 8,388,608 float4 (8192 rows x 1024 float4/row).
// Grid = 1184 blocks x 256 thr = 303,104 threads; stride S = 303,104.
// 8,388,608 / 303,104 = 27.67 -> 28 guarded iterations, unrolled 4 for MLP.
#define TOTAL_F4 8388608u

__global__ void __launch_bounds__(256) diag_scale_kernel(
        const float4* __restrict__ x, float4* __restrict__ y) {
    const unsigned int S = gridDim.x * blockDim.x;          // 303,104
    unsigned int i = blockIdx.x * blockDim.x + threadIdx.x;
    const float4* d4 = reinterpret_cast<const float4*>(g_diag);

    // Main unrolled-by-4 loop: 4 independent loads in flight per iteration.
    #pragma unroll 1
    for (; i + 3u * S < TOTAL_F4; i += 4u * S) {
        const unsigned int i0 = i, i1 = i + S, i2 = i + 2u * S, i3 = i + 3u * S;

        float4 a = __ldcs(&x[i0]);
        float4 b = __ldcs(&x[i1]);
        float4 c = __ldcs(&x[i2]);
        float4 e = __ldcs(&x[i3]);

        float4 da = __ldg(&d4[i0 & 1023u]);
        float4 db = __ldg(&d4[i1 & 1023u]);
        float4 dc = __ldg(&d4[i2 & 1023u]);
        float4 de = __ldg(&d4[i3 & 1023u]);

        a.x *= da.x; a.y *= da.y; a.z *= da.z; a.w *= da.w;
        b.x *= db.x; b.y *= db.y; b.z *= db.z; b.w *= db.w;
        c.x *= dc.x; c.y *= dc.y; c.z *= dc.z; c.w *= dc.w;
        e.x *= de.x; e.y *= de.y; e.z *= de.z; e.w *= de.w;

        __stcs(&y[i0], a);
        __stcs(&y[i1], b);
        __stcs(&y[i2], c);
        __stcs(&y[i3], e);
    }
    // Remainder (at most 3 strides worth).
    for (; i < TOTAL_F4; i += S) {
        float4 v = __ldcs(&x[i]);
        float4 d = __ldg(&d4[i & 1023u]);
        v.x *= d.x; v.y *= d.y; v.z *= d.z; v.w *= d.w;
        __stcs(&y[i], v);
    }
}

extern "C" void kernel_launch(void* const* d_in, const int* in_sizes, int n_in,
                              void* d_out, int out_size) {
    const float* x = (const float*)d_in[0];
    const float* W = (const float*)d_in[1];
    float* y = (float*)d_out;

    extract_diag_kernel<<<4, 1024>>>(W);

    // Persistent: 148 SMs x 8 blocks = 1184 blocks of 256 threads.
    diag_scale_kernel<<<1184, 256>>>((const float4*)x, (float4*)y);
}

// round 8
// speedup vs baseline: 1.0794x; 1.0794x over previous
#include <cuda_runtime.h>

// Scratch for the extracted diagonal (allocation-free: __device__ global).
__device__ float g_diag[4096];

// Kernel A: pull diag(W) out of the dense [4096,4096] matrix, then signal
// the dependent scale kernel (PDL) so its launch/prologue overlaps ours.
__global__ void extract_diag_kernel(const float* __restrict__ W) {
    int j = blockIdx.x * blockDim.x + threadIdx.x;
    if (j < 4096) {
        g_diag[j] = __ldg(&W[(size_t)j * 4097u]);
    }
    __threadfence();
    cudaTriggerProgrammaticLaunchCompletion();
}

// Kernel B: y = x * diag (columnwise), 4 linear streams, ILP=4 (R5 core).
// Total 8,388,608 float4; Q = total/4 = 2,097,152 (multiple of 1024 so all
// four elements of a thread share the same column/diag value).
#define Q 2097152u

__global__ void __launch_bounds__(256) diag_scale_kernel(
        const float4* __restrict__ x, float4* __restrict__ y) {
    const unsigned int i = blockIdx.x * blockDim.x + threadIdx.x;  // < Q

    // x-loads are independent of g_diag: issue them BEFORE the PDL sync so
    // they overlap the extract kernel's tail.
    float4 a = __ldcs(&x[i]);
    float4 b = __ldcs(&x[i + Q]);
    float4 c = __ldcs(&x[i + 2u * Q]);
    float4 e = __ldcs(&x[i + 3u * Q]);

    // Wait for extract's writes to be visible, then read the diag.
    cudaGridDependencySynchronize();
    const float4* d4 = reinterpret_cast<const float4*>(g_diag);
    const float4 d = __ldg(&d4[i & 1023u]);

    a.x *= d.x; a.y *= d.y; a.z *= d.z; a.w *= d.w;
    b.x *= d.x; b.y *= d.y; b.z *= d.z; b.w *= d.w;
    c.x *= d.x; c.y *= d.y; c.z *= d.z; c.w *= d.w;
    e.x *= d.x; e.y *= d.y; e.z *= d.z; e.w *= d.w;

    __stcs(&y[i], a);
    __stcs(&y[i + Q], b);
    __stcs(&y[i + 2u * Q], c);
    __stcs(&y[i + 3u * Q], e);
}

extern "C" void kernel_launch(void* const* d_in, const int* in_sizes, int n_in,
                              void* d_out, int out_size) {
    const float* x = (const float*)d_in[0];
    const float* W = (const float*)d_in[1];
    float* y = (float*)d_out;

    extract_diag_kernel<<<16, 256>>>(W);

    // Scale kernel with programmatic stream serialization: its launch and
    // pre-sync prologue overlap the extract kernel.
    cudaLaunchConfig_t cfg = {};
    cfg.gridDim = dim3(8192);
    cfg.blockDim = dim3(256);
    cfg.dynamicSmemBytes = 0;
    cfg.stream = 0;
    cudaLaunchAttribute attrs[1];
    attrs[0].id = cudaLaunchAttributeProgrammaticStreamSerialization;
    attrs[0].val.programmaticStreamSerializationAllowed = 1;
    cfg.attrs = attrs;
    cfg.numAttrs = 1;
    cudaLaunchKernelEx(&cfg, diag_scale_kernel, (const float4*)x, (float4*)y);
}